// round 12
// baseline (speedup 1.0000x reference)
#include <cuda_runtime.h>
#include <cstdint>

// Beam hypotheses update — scatter kernel, ballot-based per-warp meta.
// Block (j, b): all threads front-issue 4 int4 loads of SOURCE row j
// (address meta-independent). Each warp computes the destination rank with
// warp intrinsics (lane i holds board value i; rank = popc(ballot)).
// int->float conversion via magic-number LOP3+FADD (values < 2^23, exact),
// avoiding slow-pipe I2F. No smem, no barrier, 32-reg kernel.
// Output (f32, concat): len[B], worst[B], board[B,9], items[B,9,G].

#define NSLOT 9

// exact for 0 <= x < 2^23
__device__ __forceinline__ float u2f_fast(int x) {
    return __int_as_float(x | 0x4B000000) - 8388608.0f;
}

template <int VPT>
__global__ __launch_bounds__(128, 16) void beam_scatter_bal_kernel(
    const int*   __restrict__ hyp,        // [B, hyp_w]
    const float* __restrict__ slp,        // [B]
    const int*   __restrict__ lnst,       // [B]
    const float* __restrict__ worst_in,   // [B]
    const float* __restrict__ board_in,   // [B, 9]
    const int*   __restrict__ items_in,   // [B, 9, G]
    const int*   __restrict__ curlen_ptr, // scalar (may be null)
    float*       __restrict__ out,
    int batch, int hyp_w, int gen_len)
{
    const int j    = blockIdx.x;          // SOURCE slot 0..8
    const int b    = blockIdx.y;          // batch row
    const int tid  = threadIdx.x;
    const int lane = tid & 31;
    const unsigned FULL = 0xFFFFFFFFu;
    const float INF = __int_as_float(0x7F800000);

    // ---- front-batched source loads: issue before any meta work ----
    const int4* src_row = reinterpret_cast<const int4*>(
        items_in + ((size_t)b * NSLOT + j) * gen_len);
    int4 a[VPT];
#pragma unroll
    for (int it = 0; it < VPT; it++)
        a[it] = __ldcs(&src_row[tid + it * 128]);

    // ---- per-warp meta via warp intrinsics ----
    const int cur_len   = curlen_ptr ? __ldg(curlen_ptr) : hyp_w;
    const int num_beams = NSLOT - 1;

    const float score = __ldg(&slp[b]) / (float)cur_len;   // length_penalty=1
    const int   ln    = __ldg(&lnst[b]);
    const float worst = __ldg(&worst_in[b]);
    const bool  cond  = (ln < num_beams) || (score > worst);
    const int   new_len = ln + 1;
    const int   ins_idx = (new_len > NSLOT) ? 0 : num_beams;

    // lane i holds board value i (lanes >= 9 hold +INF)
    const float bi = (lane < NSLOT)
                   ? __ldg(&board_in[(size_t)b * NSLOT + lane]) : INF;
    const float vi = (lane == ins_idx) ? score : bi;

    const float vj = __shfl_sync(FULL, vi, j);
    const float bj = __shfl_sync(FULL, bi, j);   // original board[j]

    // stable rank of (vj, j): count strictly-smaller keys
    const bool pred = (lane < NSLOT) &&
                      ((vi < vj) || (vi == vj && lane < j));
    const int  r    = __popc(__ballot_sync(FULL, pred));

    const int  dest    = cond ? r : j;
    const bool use_hyp = cond && (j == ins_idx);

    // ---- scalar outputs ----
    if (tid == 0) {
        out[(size_t)2 * batch + (size_t)b * NSLOT + dest] = cond ? vj : bj;
    }
    if (j == 0 && tid < 32) {
        // two smallest of v by (value, index) via shfl reductions
        float mv = vi; int mi = lane;
#pragma unroll
        for (int off = 16; off >= 1; off >>= 1) {
            float ov = __shfl_xor_sync(FULL, mv, off);
            int   oi = __shfl_xor_sync(FULL, mi, off);
            if (ov < mv || (ov == mv && oi < mi)) { mv = ov; mi = oi; }
        }
        float sv = (lane == mi) ? INF : vi;
#pragma unroll
        for (int off = 16; off >= 1; off >>= 1)
            sv = fminf(sv, __shfl_xor_sync(FULL, sv, off));

        if (tid == 0) {
            const float new_worst =
                (new_len > num_beams) ? sv : fminf(worst, score);
            out[b]         = (float)(cond ? new_len : ln);
            out[batch + b] = cond ? new_worst : worst;
        }
    }

    // ---- hyp overlay (only the replaced source row; first cur_len elems) ----
    if (use_hyp) {
        const int* h = hyp + (size_t)b * hyp_w;
        if ((cur_len & 3) == 0 && (hyp_w & 3) == 0) {
            const int4* hyp_row = reinterpret_cast<const int4*>(h);
            const int cvec = cur_len >> 2;
#pragma unroll
            for (int it = 0; it < VPT; it++) {
                int vix = tid + it * 128;
                if (vix < cvec) a[it] = __ldg(&hyp_row[vix]);
            }
        } else {
#pragma unroll
            for (int it = 0; it < VPT; it++) {
                int base = (tid + it * 128) << 2;
                if (base + 0 < cur_len) a[it].x = h[base + 0];
                if (base + 1 < cur_len) a[it].y = h[base + 1];
                if (base + 2 < cur_len) a[it].z = h[base + 2];
                if (base + 3 < cur_len) a[it].w = h[base + 3];
            }
        }
    }

    // ---- convert (magic-number, full-rate) + scatter stores ----
    float4* dst_row = reinterpret_cast<float4*>(
        out + (size_t)batch * (2 + NSLOT) +
        ((size_t)b * NSLOT + dest) * gen_len);
#pragma unroll
    for (int it = 0; it < VPT; it++) {
        float4 f;
        f.x = u2f_fast(a[it].x); f.y = u2f_fast(a[it].y);
        f.z = u2f_fast(a[it].z); f.w = u2f_fast(a[it].w);
        __stcs(&dst_row[tid + it * 128], f);
    }
}

// ---------------- generic fallback (arbitrary gen_len) ---------------------
__global__ __launch_bounds__(128) void beam_scatter_kernel_gen(
    const int*   __restrict__ hyp,
    const float* __restrict__ slp,
    const int*   __restrict__ lnst,
    const float* __restrict__ worst_in,
    const float* __restrict__ board_in,
    const int*   __restrict__ items_in,
    const int*   __restrict__ curlen_ptr,
    float*       __restrict__ out,
    int batch, int hyp_w, int gen_len)
{
    const int j   = blockIdx.x;
    const int b   = blockIdx.y;
    const int tid = threadIdx.x;

    const int cur_len   = curlen_ptr ? __ldg(curlen_ptr) : hyp_w;
    const int num_beams = NSLOT - 1;

    const float score = __ldg(&slp[b]) / (float)cur_len;
    const int   ln    = __ldg(&lnst[b]);
    const float worst = __ldg(&worst_in[b]);
    const bool  cond  = (ln < num_beams) || (score > worst);
    const int   new_len = ln + 1;
    const int   ins_idx = (new_len > NSLOT) ? 0 : num_beams;

    float v[NSLOT];
    float binj = 0.f;
#pragma unroll
    for (int i = 0; i < NSLOT; i++) {
        v[i] = __ldg(&board_in[(size_t)b * NSLOT + i]);
        if (i == j) binj = v[i];
    }
#pragma unroll
    for (int i = 0; i < NSLOT; i++)
        if (i == ins_idx) v[i] = score;

    int r = 0;
#pragma unroll
    for (int k = 0; k < NSLOT; k++)
        if (k != j)
            r += ((v[k] < v[j]) || (v[k] == v[j] && k < j)) ? 1 : 0;

    const int  dest    = cond ? r : j;
    const bool use_hyp = cond && (j == ins_idx);

    if (tid == 0) {
        out[(size_t)2 * batch + (size_t)b * NSLOT + dest] = cond ? v[j] : binj;
        if (j == 0) {
            float m1 = v[0]; int m1i = 0;
#pragma unroll
            for (int i = 1; i < NSLOT; i++)
                if (v[i] < m1) { m1 = v[i]; m1i = i; }
            float m2 = 3.402823466e+38f;
#pragma unroll
            for (int i = 0; i < NSLOT; i++)
                if (i != m1i) m2 = fminf(m2, v[i]);
            const float new_worst =
                (new_len > num_beams) ? m2 : fminf(worst, score);
            out[b]         = (float)(cond ? new_len : ln);
            out[batch + b] = cond ? new_worst : worst;
        }
    }

    const int* src_row = items_in + ((size_t)b * NSLOT + j) * gen_len;
    float*     dst_row = out + (size_t)batch * (2 + NSLOT) +
                         ((size_t)b * NSLOT + dest) * gen_len;
    const int* h = hyp + (size_t)b * hyp_w;

    for (int e = tid; e < gen_len; e += 128) {
        int val = (use_hyp && e < cur_len) ? h[e] : __ldcs(&src_row[e]);
        __stcs(&dst_row[e], (float)val);
    }
}

extern "C" void kernel_launch(void* const* d_in, const int* in_sizes, int n_in,
                              void* d_out, int out_size)
{
    const int*   hyp    = (const int*)  d_in[0];
    const float* slp    = (const float*)d_in[1];
    const int*   lnst   = (const int*)  d_in[2];
    const float* worst  = (const float*)d_in[3];
    const float* board  = (const float*)d_in[4];
    const int*   items  = (const int*)  d_in[5];
    const int*   curlen = (n_in > 6) ? (const int*)d_in[6] : nullptr;

    const int batch   = in_sizes[1];
    const int hyp_w   = in_sizes[0] / batch;
    const int gen_len = in_sizes[5] / (batch * NSLOT);
    float* out = (float*)d_out;

    dim3 grid(NSLOT, batch);
    if (gen_len == 2048) {
        beam_scatter_bal_kernel<4><<<grid, 128>>>(
            hyp, slp, lnst, worst, board, items, curlen, out,
            batch, hyp_w, gen_len);
    } else {
        beam_scatter_kernel_gen<<<grid, 128>>>(
            hyp, slp, lnst, worst, board, items, curlen, out,
            batch, hyp_w, gen_len);
    }
}

// round 13
// speedup vs baseline: 1.0082x; 1.0082x over previous
#include <cuda_runtime.h>
#include <cstdint>

// Beam hypotheses update — single fused SCATTER kernel (round-5 structure).
// Block (j, b) reads items row j (address known at cycle 0 -> loads front-issued,
// overlapped with meta), computes the rank of slot j in the post-insert board
// with plain ALU compares (no shfl/ballot -> no MIO-pipe dependency), and
// scatters the row (int32 -> fp32 via magic-number add, full-rate) to its
// destination rank. No smem, no barrier.
// Output (f32, concat): len[B], worst[B], board[B,9], items[B,9,G].

#define NSLOT 9

// exact for 0 <= x < 2^23
__device__ __forceinline__ float u2f_fast(int x) {
    return __int_as_float(x | 0x4B000000) - 8388608.0f;
}

template <int VPT>
__global__ __launch_bounds__(128) void beam_scatter_kernel(
    const int*   __restrict__ hyp,        // [B, hyp_w]
    const float* __restrict__ slp,        // [B]
    const int*   __restrict__ lnst,       // [B]
    const float* __restrict__ worst_in,   // [B]
    const float* __restrict__ board_in,   // [B, 9]
    const int*   __restrict__ items_in,   // [B, 9, G]
    const int*   __restrict__ curlen_ptr, // scalar (may be null)
    float*       __restrict__ out,
    int batch, int hyp_w, int gen_len)
{
    const int j   = blockIdx.x;           // SOURCE slot 0..8
    const int b   = blockIdx.y;           // batch row
    const int tid = threadIdx.x;

    // ---- front-batched source loads: address independent of meta ----
    const int4* src_row = reinterpret_cast<const int4*>(
        items_in + ((size_t)b * NSLOT + j) * gen_len);
    int4 a[VPT];
#pragma unroll
    for (int it = 0; it < VPT; it++)
        a[it] = __ldcs(&src_row[tid + it * 128]);

    // ---- meta (redundant per thread; ALU-only rank, no sort) ----
    const int cur_len   = curlen_ptr ? __ldg(curlen_ptr) : hyp_w;
    const int num_beams = NSLOT - 1;

    const float score = __ldg(&slp[b]) / (float)cur_len;   // length_penalty=1
    const int   ln    = __ldg(&lnst[b]);
    const float worst = __ldg(&worst_in[b]);
    const bool  cond  = (ln < num_beams) || (score > worst);
    const int   new_len = ln + 1;
    const int   ins_idx = (new_len > NSLOT) ? 0 : num_beams;

    float v[NSLOT];
    float binj = 0.f;
#pragma unroll
    for (int i = 0; i < NSLOT; i++) {
        v[i] = __ldg(&board_in[(size_t)b * NSLOT + i]);
        if (i == j) binj = v[i];
    }
#pragma unroll
    for (int i = 0; i < NSLOT; i++)
        if (i == ins_idx) v[i] = score;

    // rank of element j under stable (value, index) ascending order
    int r = 0;
#pragma unroll
    for (int k = 0; k < NSLOT; k++)
        if (k != j)
            r += ((v[k] < v[j]) || (v[k] == v[j] && k < j)) ? 1 : 0;

    const int  dest    = cond ? r : j;
    const bool use_hyp = cond && (j == ins_idx);

    // ---- scalar outputs ----
    if (tid == 0) {
        out[(size_t)2 * batch + (size_t)b * NSLOT + dest] = cond ? v[j] : binj;
        if (j == 0) {
            // second smallest by (value, index)
            float m1 = v[0]; int m1i = 0;
#pragma unroll
            for (int i = 1; i < NSLOT; i++)
                if (v[i] < m1) { m1 = v[i]; m1i = i; }
            float m2 = 3.402823466e+38f;
#pragma unroll
            for (int i = 0; i < NSLOT; i++)
                if (i != m1i) m2 = fminf(m2, v[i]);
            const float new_worst =
                (new_len > num_beams) ? m2 : fminf(worst, score);
            out[b]         = (float)(cond ? new_len : ln);
            out[batch + b] = cond ? new_worst : worst;
        }
    }

    // ---- hyp overlay (only the replaced source row; first cur_len elems) ----
    if (use_hyp) {
        const int* h = hyp + (size_t)b * hyp_w;
        if ((cur_len & 3) == 0 && (hyp_w & 3) == 0) {
            const int4* hyp_row = reinterpret_cast<const int4*>(h);
            const int cvec = cur_len >> 2;
#pragma unroll
            for (int it = 0; it < VPT; it++) {
                int vix = tid + it * 128;
                if (vix < cvec) a[it] = __ldg(&hyp_row[vix]);
            }
        } else {
#pragma unroll
            for (int it = 0; it < VPT; it++) {
                int base = (tid + it * 128) << 2;
                if (base + 0 < cur_len) a[it].x = h[base + 0];
                if (base + 1 < cur_len) a[it].y = h[base + 1];
                if (base + 2 < cur_len) a[it].z = h[base + 2];
                if (base + 3 < cur_len) a[it].w = h[base + 3];
            }
        }
    }

    // ---- convert (magic-number, full-rate) + scatter stores ----
    float4* dst_row = reinterpret_cast<float4*>(
        out + (size_t)batch * (2 + NSLOT) +
        ((size_t)b * NSLOT + dest) * gen_len);
#pragma unroll
    for (int it = 0; it < VPT; it++) {
        float4 f;
        f.x = u2f_fast(a[it].x); f.y = u2f_fast(a[it].y);
        f.z = u2f_fast(a[it].z); f.w = u2f_fast(a[it].w);
        __stcs(&dst_row[tid + it * 128], f);
    }
}

// ---------------- generic fallback (arbitrary gen_len) ---------------------
__global__ __launch_bounds__(128) void beam_scatter_kernel_gen(
    const int*   __restrict__ hyp,
    const float* __restrict__ slp,
    const int*   __restrict__ lnst,
    const float* __restrict__ worst_in,
    const float* __restrict__ board_in,
    const int*   __restrict__ items_in,
    const int*   __restrict__ curlen_ptr,
    float*       __restrict__ out,
    int batch, int hyp_w, int gen_len)
{
    const int j   = blockIdx.x;
    const int b   = blockIdx.y;
    const int tid = threadIdx.x;

    const int cur_len   = curlen_ptr ? __ldg(curlen_ptr) : hyp_w;
    const int num_beams = NSLOT - 1;

    const float score = __ldg(&slp[b]) / (float)cur_len;
    const int   ln    = __ldg(&lnst[b]);
    const float worst = __ldg(&worst_in[b]);
    const bool  cond  = (ln < num_beams) || (score > worst);
    const int   new_len = ln + 1;
    const int   ins_idx = (new_len > NSLOT) ? 0 : num_beams;

    float v[NSLOT];
    float binj = 0.f;
#pragma unroll
    for (int i = 0; i < NSLOT; i++) {
        v[i] = __ldg(&board_in[(size_t)b * NSLOT + i]);
        if (i == j) binj = v[i];
    }
#pragma unroll
    for (int i = 0; i < NSLOT; i++)
        if (i == ins_idx) v[i] = score;

    int r = 0;
#pragma unroll
    for (int k = 0; k < NSLOT; k++)
        if (k != j)
            r += ((v[k] < v[j]) || (v[k] == v[j] && k < j)) ? 1 : 0;

    const int  dest    = cond ? r : j;
    const bool use_hyp = cond && (j == ins_idx);

    if (tid == 0) {
        out[(size_t)2 * batch + (size_t)b * NSLOT + dest] = cond ? v[j] : binj;
        if (j == 0) {
            float m1 = v[0]; int m1i = 0;
#pragma unroll
            for (int i = 1; i < NSLOT; i++)
                if (v[i] < m1) { m1 = v[i]; m1i = i; }
            float m2 = 3.402823466e+38f;
#pragma unroll
            for (int i = 0; i < NSLOT; i++)
                if (i != m1i) m2 = fminf(m2, v[i]);
            const float new_worst =
                (new_len > num_beams) ? m2 : fminf(worst, score);
            out[b]         = (float)(cond ? new_len : ln);
            out[batch + b] = cond ? new_worst : worst;
        }
    }

    const int* src_row = items_in + ((size_t)b * NSLOT + j) * gen_len;
    float*     dst_row = out + (size_t)batch * (2 + NSLOT) +
                         ((size_t)b * NSLOT + dest) * gen_len;
    const int* h = hyp + (size_t)b * hyp_w;

    for (int e = tid; e < gen_len; e += 128) {
        int val = (use_hyp && e < cur_len) ? h[e] : __ldcs(&src_row[e]);
        __stcs(&dst_row[e], (float)val);
    }
}

extern "C" void kernel_launch(void* const* d_in, const int* in_sizes, int n_in,
                              void* d_out, int out_size)
{
    const int*   hyp    = (const int*)  d_in[0];
    const float* slp    = (const float*)d_in[1];
    const int*   lnst   = (const int*)  d_in[2];
    const float* worst  = (const float*)d_in[3];
    const float* board  = (const float*)d_in[4];
    const int*   items  = (const int*)  d_in[5];
    const int*   curlen = (n_in > 6) ? (const int*)d_in[6] : nullptr;

    const int batch   = in_sizes[1];
    const int hyp_w   = in_sizes[0] / batch;
    const int gen_len = in_sizes[5] / (batch * NSLOT);
    float* out = (float*)d_out;

    dim3 grid(NSLOT, batch);
    if (gen_len == 2048) {
        beam_scatter_kernel<4><<<grid, 128>>>(
            hyp, slp, lnst, worst, board, items, curlen, out,
            batch, hyp_w, gen_len);
    } else {
        beam_scatter_kernel_gen<<<grid, 128>>>(
            hyp, slp, lnst, worst, board, items, curlen, out,
            batch, hyp_w, gen_len);
    }
}